// round 2
// baseline (speedup 1.0000x reference)
#include <cuda_runtime.h>
#include <cstdint>
#include <cstddef>

// ---------------------------------------------------------------------------
// OptimizedTop2Router — fused top-2 MoE router, exact-fp32 gate GEMM (FFMA2)
//
// Pipeline (4 launches, all graph-capturable, no allocations):
//   K0 init:  zero fp32 accumulators (g_me, g_zsum)
//   K1 gemm:  per 128-token tile: logits (fp32, f32x2-packed FFMA), softmax,
//             top-2, z partial, me partial, block-local (k,e) ranks + counts
//   K2 scan:  exclusive scan of per-tile counts across tiles -> rank offsets;
//             finalize aux_loss / z_loss scalars
//   K3 write: dispatch_mask [N,E,2] and combine_weights [N,E,2] as float,
//             fully coalesced float4 stores
//
// Output layout assumed (reference tuple order, flattened, float32):
//   [0,              N*E*2)   dispatch_mask
//   [N*E*2,        2*N*E*2)   combine_weights
//   [2*N*E*2]                 aux_loss
//   [2*N*E*2 + 1]             z_loss
// ---------------------------------------------------------------------------

#define C_DIM   2048
#define E_NUM   64
#define TB      128          // tokens per tile
#define KB      32           // K-chunk per smem stage
#define NCHUNK  (C_DIM / KB) // 64
#define XS_STRIDE 36         // padded row stride (words) for xs  (token-major)
#define WS_STRIDE2 65        // padded row stride (float2 units) for W pair tile
#define MAX_N   16384
#define MAX_BLK (MAX_N / TB) // 128

// ------------------------- scratch (static device mem) ---------------------
__device__ float  g_top2v[MAX_N * 2];     // gate values of top1/top2 per token
__device__ int2   g_top2i[MAX_N];         // expert indices of top1/top2
__device__ int    g_rank[MAX_N];          // packed: local rank k0 | (k1<<16)
__device__ int    g_bcnt[MAX_BLK * 128];  // per-tile counts  [blk][k*64+e]
__device__ int    g_boff[MAX_BLK * 128];  // exclusive offsets [blk][k*64+e]
__device__ float  g_me[E_NUM];            // sum over tokens of gate prob
__device__ float  g_zsum;                 // sum of logits^2

// packed fp32 pair FMA (Blackwell f32x2 pipe; only reachable via PTX)
__device__ __forceinline__ void fma2(unsigned long long &d,
                                     unsigned long long a,
                                     unsigned long long b)
{
    asm("fma.rn.f32x2 %0, %1, %2, %0;" : "+l"(d) : "l"(a), "l"(b));
}

// ------------------------------ K0: init -----------------------------------
__global__ void router_init_kernel()
{
    const int t = threadIdx.x;
    if (t < E_NUM) g_me[t] = 0.f;
    if (t == E_NUM) g_zsum = 0.f;
}

// ------------------------------ K1: main ------------------------------------
struct __align__(16) SmemK1 {
    union {
        struct {
            float  xs[TB * XS_STRIDE];            // 18432 B, token-major
            float2 wsp[(KB / 2) * WS_STRIDE2];    //  8320 B, k-pair-major
        } g;
        float logits[TB * 65];                     // 33280 B (padded rows)
    } u;
    float mx[TB];
    float inv_[TB];
    int   i1s[TB];
    int   i2s[TB];
    float me_s[E_NUM];
    int   cnt_s[2 * E_NUM];
    float red[256];
};

__global__ void __launch_bounds__(256, 1)
router_gemm_kernel(const float* __restrict__ x,
                   const float* __restrict__ W,
                   int N)
{
    __shared__ SmemK1 s;
    const int t  = threadIdx.x;
    const int b  = blockIdx.x;
    const int tm = t >> 4;   // token group: tokens tm*8 .. tm*8+7
    const int te = t & 15;   // expert group: experts te, te+16, te+32, te+48

    const float* __restrict__ xblk = x + (size_t)b * TB * C_DIM;

    // 32 packed accumulators: [8 tokens][4 experts], halves = even/odd K
    unsigned long long acc[8][4];
#pragma unroll
    for (int p = 0; p < 8; ++p)
#pragma unroll
        for (int j = 0; j < 4; ++j) acc[p][j] = 0ull;

    float4 xf[4];
    float2 wf[4];

    auto fetch = [&](int ck) {
#pragma unroll
        for (int i = 0; i < 4; ++i) {
            const int idx = t + i * 256;
            const int tok = idx >> 3, q = idx & 7;          // x: 128 tok x 8 vec4
            xf[i] = *(const float4*)(xblk + (size_t)tok * C_DIM + ck * KB + 4 * q);
            const int we = idx >> 4, wq = idx & 15;          // w: 64 e x 16 pairs
            wf[i] = *(const float2*)(W + (size_t)we * C_DIM + ck * KB + 2 * wq);
        }
    };

    fetch(0);

    for (int ck = 0; ck < NCHUNK; ++ck) {
        // stage chunk into smem
#pragma unroll
        for (int i = 0; i < 4; ++i) {
            const int idx = t + i * 256;
            const int tok = idx >> 3, q = idx & 7;
            *(float4*)&s.u.g.xs[tok * XS_STRIDE + 4 * q] = xf[i];
            const int we = idx >> 4, wq = idx & 15;
            s.u.g.wsp[wq * WS_STRIDE2 + we] = wf[i];
        }
        __syncthreads();

        if (ck + 1 < NCHUNK) fetch(ck + 1);   // overlap next-chunk LDG w/ math

#pragma unroll
        for (int ss = 0; ss < KB / 2; ++ss) {
            unsigned long long w2[4];
#pragma unroll
            for (int j = 0; j < 4; ++j) {
                const int e = te + 16 * j;   // strided experts -> bank-clean
                w2[j] = *(const unsigned long long*)&s.u.g.wsp[ss * WS_STRIDE2 + e];
            }
            unsigned long long x2[8];
#pragma unroll
            for (int p = 0; p < 8; ++p)
                x2[p] = *(const unsigned long long*)
                            &s.u.g.xs[(tm * 8 + p) * XS_STRIDE + 2 * ss];
#pragma unroll
            for (int p = 0; p < 8; ++p)
#pragma unroll
                for (int j = 0; j < 4; ++j)
                    fma2(acc[p][j], x2[p], w2[j]);
        }
        __syncthreads();
    }

    // ---- epilogue: unpack logits into smem (reuses GEMM staging area) ----
    float zpart = 0.f;
#pragma unroll
    for (int p = 0; p < 8; ++p)
#pragma unroll
        for (int j = 0; j < 4; ++j) {
            const unsigned long long a = acc[p][j];
            const float lo = __uint_as_float((unsigned)(a & 0xffffffffull));
            const float hi = __uint_as_float((unsigned)(a >> 32));
            const float v  = lo + hi;                 // even-K + odd-K partials
            s.u.logits[(tm * 8 + p) * 65 + (te + 16 * j)] = v;
            zpart += v * v;
        }
    if (t < 2 * E_NUM) s.cnt_s[t] = 0;
    if (t < E_NUM)     s.me_s[t]  = 0.f;
    __syncthreads();

    // ---- per-token: max, top-2, softmax denominator ----
    if (t < TB) {
        const int r = t;
        float m1 = -3.0e38f, m2 = -3.0e38f;
        int   i1 = 0, i2 = 0;
        for (int e = 0; e < E_NUM; ++e) {
            const float v = s.u.logits[r * 65 + e];
            if (v > m1)      { m2 = m1; i2 = i1; m1 = v; i1 = e; }
            else if (v > m2) { m2 = v; i2 = e; }
        }
        float sum = 0.f;
        for (int e = 0; e < E_NUM; ++e)
            sum += __expf(s.u.logits[r * 65 + e] - m1);
        const float inv = 1.0f / sum;
        s.mx[r] = m1; s.inv_[r] = inv; s.i1s[r] = i1; s.i2s[r] = i2;
        const int n = b * TB + r;
        g_top2i[n] = make_int2(i1, i2);
        ((float2*)g_top2v)[n] = make_float2(inv, __expf(m2 - m1) * inv);
    }
    __syncthreads();

    // ---- local ranks (token order within tile) + tile counts ----
    if (t < TB) {
        const int r = t;
        const int i1 = s.i1s[r], i2 = s.i2s[r];
        int r0 = 0, r1 = 0;
        for (int t2 = 0; t2 < r; ++t2) {
            r0 += (s.i1s[t2] == i1);
            r1 += (s.i2s[t2] == i2);
        }
        g_rank[b * TB + r] = r0 | (r1 << 16);
        atomicAdd(&s.cnt_s[i1], 1);
        atomicAdd(&s.cnt_s[E_NUM + i2], 1);
    }

    // ---- me partial: thread (e, token-quarter) sums 32 gate probs ----
    {
        const int e = t & 63, gq = t >> 6;
        float part = 0.f;
        for (int i = 0; i < 32; ++i) {
            const int r2 = gq * 32 + i;
            part += __expf(s.u.logits[r2 * 65 + e] - s.mx[r2]) * s.inv_[r2];
        }
        atomicAdd(&s.me_s[e], part);
    }

    // ---- z reduce (also fences the atomics above) ----
    s.red[t] = zpart;
    __syncthreads();
#pragma unroll
    for (int off = 128; off >= 1; off >>= 1) {
        if (t < off) s.red[t] += s.red[t + off];
        __syncthreads();
    }
    if (t == 0) atomicAdd(&g_zsum, s.red[0]);

    if (t < 2 * E_NUM) g_bcnt[b * 128 + t] = s.cnt_s[t];
    if (t < E_NUM)     atomicAdd(&g_me[t], s.me_s[t]);
}

// --------------------- K2: inter-tile scan + scalars ------------------------
__global__ void router_scan_kernel(float* __restrict__ out,
                                   int N, int nblk, int ne2)
{
    const int j = threadIdx.x;       // (k,e) pair: j = k*64 + e, 0..127
    int run = 0;
    for (int bb = 0; bb < nblk; ++bb) {
        const int c = g_bcnt[bb * 128 + j];
        g_boff[bb * 128 + j] = run;
        run += c;
    }
    __shared__ float red[128];
    float part = 0.f;
    if (j < E_NUM) part = g_me[j] * (float)run;   // run == total top-1 count_e
    red[j] = part;
    __syncthreads();
#pragma unroll
    for (int off = 64; off >= 1; off >>= 1) {
        if (j < off) red[j] += red[j + off];
        __syncthreads();
    }
    if (j == 0) {
        const float nn = (float)N;
        out[(size_t)2 * ne2]     = (float)E_NUM * red[0] / (nn * nn); // aux
        out[(size_t)2 * ne2 + 1] = g_zsum / (nn * (float)E_NUM);      // z
    }
}

// ------------------------- K3: output writer --------------------------------
__global__ void __launch_bounds__(256)
router_write_kernel(float* __restrict__ out, int N, int capacity)
{
    const int b    = blockIdx.x;
    const int warp = threadIdx.x >> 5;
    const int lane = threadIdx.x & 31;
    float* __restrict__ dmo = out;                         // dispatch [N,E,2]
    float* __restrict__ cwo = out + (size_t)N * 128;       // combine  [N,E,2]

    for (int i = 0; i < 16; ++i) {
        const int n  = b * TB + warp * 16 + i;
        const int2  ij = g_top2i[n];
        const float2 vv = ((const float2*)g_top2v)[n];
        const int rk  = g_rank[n];
        const int blk = n >> 7;
        const int pos0 = g_boff[blk * 128 + ij.x]          + (rk & 0xffff);
        const int pos1 = g_boff[blk * 128 + E_NUM + ij.y]  + (rk >> 16);
        const bool k0 = pos0 < capacity;
        const bool k1 = pos1 < capacity;
        const int e0 = lane * 2, e1 = e0 + 1;
        const float d00 = (k0 && ij.x == e0) ? 1.f : 0.f;
        const float d01 = (k1 && ij.y == e0) ? 1.f : 0.f;
        const float d10 = (k0 && ij.x == e1) ? 1.f : 0.f;
        const float d11 = (k1 && ij.y == e1) ? 1.f : 0.f;
        const float4 dm = make_float4(d00, d01, d10, d11);
        const float4 cw = make_float4(d00 * vv.x, d01 * vv.y,
                                      d10 * vv.x, d11 * vv.y);
        ((float4*)dmo)[(size_t)n * 32 + lane] = dm;   // 512B/warp, coalesced
        ((float4*)cwo)[(size_t)n * 32 + lane] = cw;
    }
}

// ------------------------------ launch --------------------------------------
extern "C" void kernel_launch(void* const* d_in, const int* in_sizes, int n_in,
                              void* d_out, int out_size)
{
    const float* x = (const float*)d_in[0];   // [4,4096,2048] f32
    const float* W = (const float*)d_in[1];   // [64,2048]     f32
    float* out = (float*)d_out;

    const int N    = in_sizes[0] / C_DIM;     // 16384
    const int nblk = N / TB;                  // 128
    const int ne2  = N * E_NUM * 2;           // 2,097,152
    const int capacity = (int)(1.25 * (double)N * 2.0 / (double)E_NUM); // 640

    router_init_kernel<<<1, 128>>>();
    router_gemm_kernel<<<nblk, 256>>>(x, W, N);
    router_scan_kernel<<<1, 128>>>(out, N, nblk, ne2);
    router_write_kernel<<<nblk, 256>>>(out, N, capacity);
}

// round 5
// speedup vs baseline: 1.2413x; 1.2413x over previous
#include <cuda_runtime.h>
#include <cstdint>
#include <cstddef>

#define C_DIM 2048
#define E_NUM 64
#define TB    128
#define MAX_N 16384
#define MAX_BLK (MAX_N / TB)
#define NCHUNK 32                    // K chunks of 64 floats
#define A_ROW_F 68                   // padded A row stride (floats)
#define A_BUF   34816                // 128 * 68 * 4
#define W_BUF   32768                // per-chunk W frags (hi+lo)
#define A0_OFF  0
#define W0_OFF  (2 * A_BUF)          // 69632
#define TAIL    (2 * A_BUF + 2 * W_BUF)   // 135168
#define INV_OFF (TAIL + 0)
#define I1_OFF  (TAIL + 512)
#define I2_OFF  (TAIL + 1024)
#define MES_OFF (TAIL + 1536)
#define CNT_OFF (TAIL + 1792)
#define RED_OFF (TAIL + 2304)
#define DYN_BYTES (TAIL + 2432)

__device__ float2 g_wf[131072];          // 1MB: [ck][term][ks][nt][lane] B-frags
__device__ float  g_top2v[MAX_N * 2];
__device__ int2   g_top2i[MAX_N];
__device__ int    g_rank[MAX_N];
__device__ int    g_bcnt[MAX_BLK * 128];
__device__ int    g_boff[MAX_BLK * 128];
__device__ float  g_me[E_NUM];
__device__ float  g_zsum;

__device__ __forceinline__ uint32_t smem_u32(const void* p) {
    uint32_t a;
    asm("{ .reg .u64 t; cvta.to.shared.u64 t, %1; cvt.u32.u64 %0, t; }"
        : "=r"(a) : "l"(p));
    return a;
}
__device__ __forceinline__ uint32_t tf32_of(float v) {
    uint32_t r;
    asm("cvt.rna.tf32.f32 %0, %1;" : "=r"(r) : "f"(v));
    return r;
}
__device__ __forceinline__ void mma8(float* c, const uint32_t* a,
                                     const uint32_t* b) {
    asm volatile(
        "mma.sync.aligned.m16n8k8.row.col.f32.tf32.tf32.f32 "
        "{%0,%1,%2,%3}, {%4,%5,%6,%7}, {%8,%9}, {%0,%1,%2,%3};"
        : "+f"(c[0]), "+f"(c[1]), "+f"(c[2]), "+f"(c[3])
        : "r"(a[0]), "r"(a[1]), "r"(a[2]), "r"(a[3]), "r"(b[0]), "r"(b[1]));
}
#define CP16(d, s) \
    asm volatile("cp.async.cg.shared.global [%0], [%1], 16;" \
                 :: "r"((uint32_t)(d)), "l"(s) : "memory")
#define CP_COMMIT() asm volatile("cp.async.commit_group;" ::: "memory")

__global__ void router_init_kernel()
{
    const int t = threadIdx.x;
    if (t < E_NUM) g_me[t] = 0.f;
    if (t == E_NUM) g_zsum = 0.f;
}

// Prebake W into per-lane mma B-fragment order, tf32 hi (term0) / lo (term1).
// float2 index = ck*4096 + term*2048 + ks*256 + nt*32 + lane
// b0 = W[n][k], b1 = W[n][k+4], n = nt*8 + lane/4, k = ck*64 + ks*8 + lane%4
__global__ void __launch_bounds__(256)
router_prep_kernel(const float* __restrict__ W)
{
    const int tid = blockIdx.x * 256 + threadIdx.x;   // 0..131071
    const int ck = tid >> 12, r = tid & 4095;
    const int term = r >> 11, r2 = r & 2047;
    const int ks = r2 >> 8, rr = r2 & 255;
    const int nt = rr >> 5, l = rr & 31;
    const int n = nt * 8 + (l >> 2);
    const int k = ck * 64 + ks * 8 + (l & 3);
    const float w0 = W[n * C_DIM + k];
    const float w1 = W[n * C_DIM + k + 4];
    const uint32_t h0 = tf32_of(w0), h1 = tf32_of(w1);
    float2 v;
    if (term == 0) {
        v = make_float2(__uint_as_float(h0), __uint_as_float(h1));
    } else {
        v = make_float2(
            __uint_as_float(tf32_of(w0 - __uint_as_float(h0))),
            __uint_as_float(tf32_of(w1 - __uint_as_float(h1))));
    }
    g_wf[tid] = v;
}

__global__ void __launch_bounds__(256, 1)
router_gemm_kernel(const float* __restrict__ x, int N)
{
    extern __shared__ char sm[];
    const uint32_t smb = smem_u32(sm);
    const int t = threadIdx.x, b = blockIdx.x;
    const int w = t >> 5, l = t & 31;
    const int m0 = (w & 3) * 32, nh = w >> 2;
    const float* __restrict__ xblk = x + (size_t)b * TB * C_DIM;

    float c[2][4][4];
#pragma unroll
    for (int mt = 0; mt < 2; ++mt)
#pragma unroll
        for (int j = 0; j < 4; ++j)
#pragma unroll
            for (int q = 0; q < 4; ++q) c[mt][j][q] = 0.f;

    auto issue = [&](int ck) {
        const uint32_t ab = smb + A0_OFF + (ck & 1) * A_BUF;
        const uint32_t wb = smb + W0_OFF + (ck & 1) * W_BUF;
#pragma unroll
        for (int i = 0; i < 8; ++i) {          // A: 128 tok x 64 k, padded rows
            const int u = t + i * 256, tok = u >> 4, k16 = u & 15;
            CP16(ab + tok * (A_ROW_F * 4) + k16 * 16,
                 (const void*)(xblk + (size_t)tok * C_DIM + ck * 64 + k16 * 4));
        }
#pragma unroll
        for (int i = 0; i < 8; ++i) {          // W frags: contiguous 32KB
            const int u = t + i * 256;
            CP16(wb + u * 16, (const void*)(g_wf + ck * 4096 + u * 2));
        }
        CP_COMMIT();
    };

    issue(0);

    for (int ck = 0; ck < NCHUNK; ++ck) {
        if (ck + 1 < NCHUNK) {
            issue(ck + 1);
            asm volatile("cp.async.wait_group 1;" ::: "memory");
        } else {
            asm volatile("cp.async.wait_group 0;" ::: "memory");
        }
        __syncthreads();

        const char* ab = sm + A0_OFF + (ck & 1) * A_BUF;
        const char* wb = sm + W0_OFF + (ck & 1) * W_BUF;

#pragma unroll
        for (int ks = 0; ks < 8; ++ks) {
            uint32_t aH[2][4], aL[2][4];
#pragma unroll
            for (int mt = 0; mt < 2; ++mt) {
                const int r0 = m0 + mt * 16 + (l >> 2);
                const int k0 = ks * 8 + (l & 3);
                const float v0 = *(const float*)(ab + (r0 * A_ROW_F + k0) * 4);
                const float v1 = *(const float*)(ab + ((r0 + 8) * A_ROW_F + k0) * 4);
                const float v2 = *(const float*)(ab + (r0 * A_ROW_F + k0 + 4) * 4);
                const float v3 = *(const float*)(ab + ((r0 + 8) * A_ROW_F + k0 + 4) * 4);
                aH[mt][0] = tf32_of(v0); aH[mt][1] = tf32_of(v1);
                aH[mt][2] = tf32_of(v2); aH[mt][3] = tf32_of(v3);
                aL[mt][0] = tf32_of(v0 - __uint_as_float(aH[mt][0]));
                aL[mt][1] = tf32_of(v1 - __uint_as_float(aH[mt][1]));
                aL[mt][2] = tf32_of(v2 - __uint_as_float(aH[mt][2]));
                aL[mt][3] = tf32_of(v3 - __uint_as_float(aH[mt][3]));
            }
            uint32_t bH[4][2], bL[4][2];
#pragma unroll
            for (int j = 0; j < 4; ++j) {
                const int nt = nh * 4 + j;
                const uint2 h = *(const uint2*)(wb + ((0 * 8 + ks) * 8 + nt) * 256 + l * 8);
                const uint2 lo = *(const uint2*)(wb + ((1 * 8 + ks) * 8 + nt) * 256 + l * 8);
                bH[j][0] = h.x;  bH[j][1] = h.y;
                bL[j][0] = lo.x; bL[j][1] = lo.y;
            }
#pragma unroll
            for (int mt = 0; mt < 2; ++mt)
#pragma unroll
                for (int j = 0; j < 4; ++j) {
                    mma8(c[mt][j], aH[mt], bH[j]);
                    mma8(c[mt][j], aL[mt], bH[j]);
                    mma8(c[mt][j], aH[mt], bL[j]);
                }
        }
        __syncthreads();
    }

    // ---------------- epilogue ----------------
    float* LG   = (float*)sm;                  // [128][65], overlays dead bufs
    float* INVp = (float*)(sm + INV_OFF);
    int*   I1   = (int*)(sm + I1_OFF);
    int*   I2   = (int*)(sm + I2_OFF);
    float* MES  = (float*)(sm + MES_OFF);
    int*   CNT  = (int*)(sm + CNT_OFF);
    float* RED  = (float*)(sm + RED_OFF);

    float zpart = 0.f;
#pragma unroll
    for (int mt = 0; mt < 2; ++mt)
#pragma unroll
        for (int j = 0; j < 4; ++j)
#pragma unroll
            for (int q = 0; q < 4; ++q) zpart += c[mt][j][q] * c[mt][j][q];

#pragma unroll
    for (int mt = 0; mt < 2; ++mt)
#pragma unroll
        for (int ro = 0; ro < 2; ++ro)
#pragma unroll
            for (int j = 0; j < 4; ++j)
#pragma unroll
                for (int cp = 0; cp < 2; ++cp) {
                    const int row = m0 + mt * 16 + (l >> 2) + ro * 8;
                    const int col = nh * 32 + j * 8 + (l & 3) * 2 + cp;
                    LG[row * 65 + col] = c[mt][j][ro * 2 + cp];
                }
    if (t < 128) CNT[t] = 0;
    if (t >= 128 && t < 192) MES[t - 128] = 0.f;
    if (t == 254) RED[0] = 0.f;
    __syncthreads();

    atomicAdd(&RED[0], zpart);    // all 256 threads; smem atomic
    if (t < 128) {
        float m1 = -3.0e38f, m2 = -3.0e38f;
        int i1 = 0, i2 = 0;
        for (int e = 0; e < 64; ++e) {
            const float v = LG[t * 65 + e];
            if (v > m1)      { m2 = m1; i2 = i1; m1 = v; i1 = e; }
            else if (v > m2) { m2 = v; i2 = e; }
        }
        float sum = 0.f;
        for (int e = 0; e < 64; ++e)
            sum += __expf(LG[t * 65 + e] - m1);
        const float inv = 1.0f / sum;
        INVp[t] = inv; I1[t] = i1; I2[t] = i2;
        // store (max, inv) for me pass; write token outputs
        const int n = b * TB + t;
        g_top2i[n] = make_int2(i1, i2);
        ((float2*)g_top2v)[n] = make_float2(inv, __expf(m2 - m1) * inv);
        LG[t * 65 + 64] = m1;     // stash row max in pad column
    }
    __syncthreads();

    if (t < 128) {                // local (k,e) ranks within the tile
        const int i1 = I1[t], i2 = I2[t];
        int r0 = 0, r1 = 0;
        for (int t2 = 0; t2 < t; ++t2) {
            r0 += (I1[t2] == i1);
            r1 += (I2[t2] == i2);
        }
        g_rank[b * TB + t] = r0 | (r1 << 16);
        atomicAdd(&CNT[i1], 1);
        atomicAdd(&CNT[64 + i2], 1);
    }
    {                             // me partials: (expert, token-half) threads
        const int e = t & 63, gq = t >> 6;
        float part = 0.f;
        for (int i = 0; i < 32; ++i) {
            const int r2 = gq * 32 + i;
            part += __expf(LG[r2 * 65 + e] - LG[r2 * 65 + 64]) * INVp[r2];
        }
        atomicAdd(&MES[e], part);
    }
    __syncthreads();
    if (t < 128) g_bcnt[b * 128 + t] = CNT[t];
    if (t >= 128 && t < 192) atomicAdd(&g_me[t - 128], MES[t - 128]);
    if (t == 254) atomicAdd(&g_zsum, RED[0]);
}

__global__ void router_scan_kernel(float* __restrict__ out,
                                   int N, int nblk, int ne2)
{
    const int j = threadIdx.x;
    int run = 0;
    for (int bb = 0; bb < nblk; ++bb) {
        g_boff[bb * 128 + j] = run;
        run += g_bcnt[bb * 128 + j];
    }
    __shared__ float red[128];
    red[j] = (j < E_NUM) ? g_me[j] * (float)run : 0.f;
    __syncthreads();
#pragma unroll
    for (int off = 64; off >= 1; off >>= 1) {
        if (j < off) red[j] += red[j + off];
        __syncthreads();
    }
    if (j == 0) {
        const float nn = (float)N;
        out[(size_t)2 * ne2]     = (float)E_NUM * red[0] / (nn * nn);
        out[(size_t)2 * ne2 + 1] = g_zsum / (nn * (float)E_NUM);
    }
}

__global__ void __launch_bounds__(256)
router_write_kernel(float* __restrict__ out, int N, int capacity)
{
    const int b = blockIdx.x;
    const int warp = threadIdx.x >> 5, lane = threadIdx.x & 31;
    float* __restrict__ dmo = out;
    float* __restrict__ cwo = out + (size_t)N * 128;

#pragma unroll
    for (int i = 0; i < 4; ++i) {
        const int n = b * 32 + warp * 4 + i;
        const int2 ij = g_top2i[n];
        const float2 vv = ((const float2*)g_top2v)[n];
        const int rk = g_rank[n], blk = n >> 7;
        const bool k0 = (g_boff[blk * 128 + ij.x]         + (rk & 0xffff)) < capacity;
        const bool k1 = (g_boff[blk * 128 + E_NUM + ij.y] + (rk >> 16))   < capacity;
        const int e0 = lane * 2, e1 = e0 + 1;
        const float d00 = (k0 && ij.x == e0) ? 1.f : 0.f;
        const float d01 = (k1 && ij.y == e0) ? 1.f : 0.f;
        const float d10 = (k0 && ij.x == e1) ? 1.f : 0.f;
        const float d11 = (k1 && ij.y == e1) ? 1.f : 0.f;
        ((float4*)dmo)[(size_t)n * 32 + lane] = make_float4(d00, d01, d10, d11);
        ((float4*)cwo)[(size_t)n * 32 + lane] =
            make_float4(d00 * vv.x, d01 * vv.y, d10 * vv.x, d11 * vv.y);
    }
}

extern "C" void kernel_launch(void* const* d_in, const int* in_sizes, int n_in,
                              void* d_out, int out_size)
{
    const float* x = (const float*)d_in[0];   // [4,4096,2048] f32
    const float* W = (const float*)d_in[1];   // [64,2048]     f32
    float* out = (float*)d_out;

    const int N    = in_sizes[0] / C_DIM;     // 16384
    const int nblk = N / TB;                  // 128
    const int ne2  = N * E_NUM * 2;
    const int capacity = (int)(1.25 * (double)N * 2.0 / (double)E_NUM); // 640

    cudaFuncSetAttribute(router_gemm_kernel,
                         cudaFuncAttributeMaxDynamicSharedMemorySize, DYN_BYTES);

    router_init_kernel<<<1, 128>>>();
    router_prep_kernel<<<512, 256>>>(W);
    router_gemm_kernel<<<nblk, 256, DYN_BYTES>>>(x, N);
    router_scan_kernel<<<1, 128>>>(out, N, nblk, ne2);
    router_write_kernel<<<N / 32, 256>>>(out, N, capacity);
}

// round 7
// speedup vs baseline: 1.4948x; 1.2042x over previous
#include <cuda_runtime.h>
#include <cstdint>
#include <cstddef>

#define C_DIM 2048
#define E_NUM 64
#define TB    128
#define MAX_N 16384
#define MAX_BLK (MAX_N / TB)
#define NCHUNK 32                    // K chunks of 64 floats
#define A_ROW_F 68                   // padded A row stride (floats)
#define A_BUF   34816                // 128 * 68 * 4
#define W_BUF   32768                // per-chunk W frags (hi+lo)
#define A0_OFF  0
#define W0_OFF  (2 * A_BUF)          // 69632
#define TAIL    (2 * A_BUF + 2 * W_BUF)   // 135168
#define INV_OFF (TAIL + 0)
#define I1_OFF  (TAIL + 512)
#define I2_OFF  (TAIL + 1024)
#define MES_OFF (TAIL + 1536)
#define CNT_OFF (TAIL + 1792)
#define RED_OFF (TAIL + 2304)
#define DYN_BYTES (TAIL + 2432)

__device__ float2 g_wf[131072];          // 1MB: [ck][term][ks][nt][lane] B-frags
__device__ float  g_top2v[MAX_N * 2];
__device__ int2   g_top2i[MAX_N];
__device__ int    g_rank[MAX_N];
__device__ int    g_bcnt[MAX_BLK * 128];
__device__ int    g_boff[MAX_BLK * 128];
__device__ float  g_me[E_NUM];
__device__ float  g_zsum;

__device__ __forceinline__ uint32_t smem_u32(const void* p) {
    uint32_t a;
    asm("{ .reg .u64 t; cvta.to.shared.u64 t, %1; cvt.u32.u64 %0, t; }"
        : "=r"(a) : "l"(p));
    return a;
}
__device__ __forceinline__ uint32_t tf32_of(float v) {
    uint32_t r;
    asm("cvt.rna.tf32.f32 %0, %1;" : "=r"(r) : "f"(v));
    return r;
}
__device__ __forceinline__ void mma8(float* c, const uint32_t* a,
                                     const uint32_t* b) {
    asm volatile(
        "mma.sync.aligned.m16n8k8.row.col.f32.tf32.tf32.f32 "
        "{%0,%1,%2,%3}, {%4,%5,%6,%7}, {%8,%9}, {%0,%1,%2,%3};"
        : "+f"(c[0]), "+f"(c[1]), "+f"(c[2]), "+f"(c[3])
        : "r"(a[0]), "r"(a[1]), "r"(a[2]), "r"(a[3]), "r"(b[0]), "r"(b[1]));
}
#define CP16(d, s) \
    asm volatile("cp.async.cg.shared.global [%0], [%1], 16;" \
                 :: "r"((uint32_t)(d)), "l"(s) : "memory")
#define CP_COMMIT() asm volatile("cp.async.commit_group;" ::: "memory")

__global__ void router_init_kernel()
{
    const int t = threadIdx.x;
    if (t < E_NUM) g_me[t] = 0.f;
    if (t == E_NUM) g_zsum = 0.f;
}

// Prebake W into per-lane mma B-fragment order, tf32 hi (term0) / lo (term1).
// float2 index = ck*4096 + term*2048 + ks*256 + nt*32 + lane
// b0 = W[n][k], b1 = W[n][k+4], n = nt*8 + lane/4, k = ck*64 + ks*8 + lane%4
__global__ void __launch_bounds__(256)
router_prep_kernel(const float* __restrict__ W)
{
    const int tid = blockIdx.x * 256 + threadIdx.x;   // 0..131071
    const int ck = tid >> 12, r = tid & 4095;
    const int term = r >> 11, r2 = r & 2047;
    const int ks = r2 >> 8, rr = r2 & 255;
    const int nt = rr >> 5, l = rr & 31;
    const int n = nt * 8 + (l >> 2);
    const int k = ck * 64 + ks * 8 + (l & 3);
    const float w0 = W[n * C_DIM + k];
    const float w1 = W[n * C_DIM + k + 4];
    const uint32_t h0 = tf32_of(w0), h1 = tf32_of(w1);
    float2 v;
    if (term == 0) {
        v = make_float2(__uint_as_float(h0), __uint_as_float(h1));
    } else {
        v = make_float2(
            __uint_as_float(tf32_of(w0 - __uint_as_float(h0))),
            __uint_as_float(tf32_of(w1 - __uint_as_float(h1))));
    }
    g_wf[tid] = v;
}

__global__ void __launch_bounds__(256, 1)
router_gemm_kernel(const float* __restrict__ x, int N)
{
    extern __shared__ char sm[];
    const uint32_t smb = smem_u32(sm);
    const int t = threadIdx.x, b = blockIdx.x;
    const int w = t >> 5, l = t & 31;
    const int m0 = (w & 3) * 32, nh = w >> 2;
    const float* __restrict__ xblk = x + (size_t)b * TB * C_DIM;

    float c[2][4][4];
#pragma unroll
    for (int mt = 0; mt < 2; ++mt)
#pragma unroll
        for (int j = 0; j < 4; ++j)
#pragma unroll
            for (int q = 0; q < 4; ++q) c[mt][j][q] = 0.f;

    auto issue = [&](int ck) {
        const uint32_t ab = smb + A0_OFF + (ck & 1) * A_BUF;
        const uint32_t wb = smb + W0_OFF + (ck & 1) * W_BUF;
#pragma unroll
        for (int i = 0; i < 8; ++i) {          // A: 128 tok x 64 k, padded rows
            const int u = t + i * 256, tok = u >> 4, k16 = u & 15;
            CP16(ab + tok * (A_ROW_F * 4) + k16 * 16,
                 (const void*)(xblk + (size_t)tok * C_DIM + ck * 64 + k16 * 4));
        }
#pragma unroll
        for (int i = 0; i < 8; ++i) {          // W frags: contiguous 32KB
            const int u = t + i * 256;
            CP16(wb + u * 16, (const void*)(g_wf + ck * 4096 + u * 2));
        }
        CP_COMMIT();
    };

    issue(0);

    for (int ck = 0; ck < NCHUNK; ++ck) {
        if (ck + 1 < NCHUNK) {
            issue(ck + 1);
            asm volatile("cp.async.wait_group 1;" ::: "memory");
        } else {
            asm volatile("cp.async.wait_group 0;" ::: "memory");
        }
        __syncthreads();

        const char* ab = sm + A0_OFF + (ck & 1) * A_BUF;
        const char* wb = sm + W0_OFF + (ck & 1) * W_BUF;

#pragma unroll
        for (int ks = 0; ks < 8; ++ks) {
            uint32_t aH[2][4], aL[2][4];
#pragma unroll
            for (int mt = 0; mt < 2; ++mt) {
                const int r0 = m0 + mt * 16 + (l >> 2);
                const int k0 = ks * 8 + (l & 3);
                const float v0 = *(const float*)(ab + (r0 * A_ROW_F + k0) * 4);
                const float v1 = *(const float*)(ab + ((r0 + 8) * A_ROW_F + k0) * 4);
                const float v2 = *(const float*)(ab + (r0 * A_ROW_F + k0 + 4) * 4);
                const float v3 = *(const float*)(ab + ((r0 + 8) * A_ROW_F + k0 + 4) * 4);
                aH[mt][0] = tf32_of(v0); aH[mt][1] = tf32_of(v1);
                aH[mt][2] = tf32_of(v2); aH[mt][3] = tf32_of(v3);
                aL[mt][0] = tf32_of(v0 - __uint_as_float(aH[mt][0]));
                aL[mt][1] = tf32_of(v1 - __uint_as_float(aH[mt][1]));
                aL[mt][2] = tf32_of(v2 - __uint_as_float(aH[mt][2]));
                aL[mt][3] = tf32_of(v3 - __uint_as_float(aH[mt][3]));
            }
            uint32_t bH[4][2], bL[4][2];
#pragma unroll
            for (int j = 0; j < 4; ++j) {
                const int nt = nh * 4 + j;
                const uint2 h = *(const uint2*)(wb + ((0 * 8 + ks) * 8 + nt) * 256 + l * 8);
                const uint2 lo = *(const uint2*)(wb + ((1 * 8 + ks) * 8 + nt) * 256 + l * 8);
                bH[j][0] = h.x;  bH[j][1] = h.y;
                bL[j][0] = lo.x; bL[j][1] = lo.y;
            }
#pragma unroll
            for (int mt = 0; mt < 2; ++mt)
#pragma unroll
                for (int j = 0; j < 4; ++j) {
                    mma8(c[mt][j], aH[mt], bH[j]);
                    mma8(c[mt][j], aL[mt], bH[j]);
                    mma8(c[mt][j], aH[mt], bL[j]);
                }
        }
        __syncthreads();
    }

    // ---------------- epilogue ----------------
    float* LG   = (float*)sm;                  // [128][65], overlays dead bufs
    float* INVp = (float*)(sm + INV_OFF);
    int*   I1   = (int*)(sm + I1_OFF);
    int*   I2   = (int*)(sm + I2_OFF);
    float* MES  = (float*)(sm + MES_OFF);
    int*   CNT  = (int*)(sm + CNT_OFF);
    float* RED  = (float*)(sm + RED_OFF);

    float zpart = 0.f;
#pragma unroll
    for (int mt = 0; mt < 2; ++mt)
#pragma unroll
        for (int j = 0; j < 4; ++j)
#pragma unroll
            for (int q = 0; q < 4; ++q) zpart += c[mt][j][q] * c[mt][j][q];

#pragma unroll
    for (int mt = 0; mt < 2; ++mt)
#pragma unroll
        for (int ro = 0; ro < 2; ++ro)
#pragma unroll
            for (int j = 0; j < 4; ++j)
#pragma unroll
                for (int cp = 0; cp < 2; ++cp) {
                    const int row = m0 + mt * 16 + (l >> 2) + ro * 8;
                    const int col = nh * 32 + j * 8 + (l & 3) * 2 + cp;
                    LG[row * 65 + col] = c[mt][j][ro * 2 + cp];
                }
    if (t < 128) CNT[t] = 0;
    if (t >= 128 && t < 192) MES[t - 128] = 0.f;
    if (t == 254) RED[0] = 0.f;
    __syncthreads();

    atomicAdd(&RED[0], zpart);    // all 256 threads; smem atomic
    if (t < 128) {
        float m1 = -3.0e38f, m2 = -3.0e38f;
        int i1 = 0, i2 = 0;
        for (int e = 0; e < 64; ++e) {
            const float v = LG[t * 65 + e];
            if (v > m1)      { m2 = m1; i2 = i1; m1 = v; i1 = e; }
            else if (v > m2) { m2 = v; i2 = e; }
        }
        float sum = 0.f;
        for (int e = 0; e < 64; ++e)
            sum += __expf(LG[t * 65 + e] - m1);
        const float inv = 1.0f / sum;
        INVp[t] = inv; I1[t] = i1; I2[t] = i2;
        const int n = b * TB + t;
        g_top2i[n] = make_int2(i1, i2);
        ((float2*)g_top2v)[n] = make_float2(inv, __expf(m2 - m1) * inv);
        LG[t * 65 + 64] = m1;     // stash row max in pad column
    }
    __syncthreads();

    if (t < 128) {                // local (k,e) ranks within the tile
        const int i1 = I1[t], i2 = I2[t];
        int r0 = 0, r1 = 0;
        for (int t2 = 0; t2 < t; ++t2) {
            r0 += (I1[t2] == i1);
            r1 += (I2[t2] == i2);
        }
        g_rank[b * TB + t] = r0 | (r1 << 16);
        atomicAdd(&CNT[i1], 1);
        atomicAdd(&CNT[64 + i2], 1);
    }
    {                             // me partials: (expert, token-half) threads
        const int e = t & 63, gq = t >> 6;
        float part = 0.f;
        for (int i = 0; i < 32; ++i) {
            const int r2 = gq * 32 + i;
            part += __expf(LG[r2 * 65 + e] - LG[r2 * 65 + 64]) * INVp[r2];
        }
        atomicAdd(&MES[e], part);
    }
    __syncthreads();
    if (t < 128) g_bcnt[b * 128 + t] = CNT[t];
    if (t >= 128 && t < 192) atomicAdd(&g_me[t - 128], MES[t - 128]);
    if (t == 254) atomicAdd(&g_zsum, RED[0]);
}

// Parallel inter-tile scan: 512 threads = 4 segments x 128 (k,e) pairs.
// Each thread: 32 INDEPENDENT loads (one latency exposure), local exclusive
// prefix in registers, segment offsets via smem, 32 independent stores.
// Thread 0 then computes both scalar losses from smem-resident totals.
__global__ void __launch_bounds__(512)
router_scan_kernel(float* __restrict__ out, int N, int nblk, int ne2)
{
    const int j   = threadIdx.x & 127;     // (k,e) pair
    const int seg = threadIdx.x >> 7;      // 0..3, 32 tiles each
    const int sblk = nblk >> 2;            // 32

    int cnt[32];
#pragma unroll
    for (int i = 0; i < 32; ++i)           // coalesced, independent LDGs
        cnt[i] = g_bcnt[(seg * sblk + i) * 128 + j];

    int run = 0;
#pragma unroll
    for (int i = 0; i < 32; ++i) { const int c = cnt[i]; cnt[i] = run; run += c; }

    __shared__ int stot[4][128];
    stot[seg][j] = run;
    __syncthreads();

    int base = 0;
#pragma unroll
    for (int s2 = 0; s2 < 4; ++s2)
        if (s2 < seg) base += stot[s2][j];
#pragma unroll
    for (int i = 0; i < 32; ++i)
        g_boff[(seg * sblk + i) * 128 + j] = base + cnt[i];

    if (threadIdx.x == 0) {
        float aux = 0.f;
        for (int e = 0; e < E_NUM; ++e) {
            const int te = stot[0][e] + stot[1][e] + stot[2][e] + stot[3][e];
            aux += g_me[e] * (float)te;    // te = total top-1 count of expert e
        }
        const float nn = (float)N;
        out[(size_t)2 * ne2]     = (float)E_NUM * aux / (nn * nn);
        out[(size_t)2 * ne2 + 1] = g_zsum / (nn * (float)E_NUM);
    }
}

__global__ void __launch_bounds__(256)
router_write_kernel(float* __restrict__ out, int N, int capacity)
{
    const int b = blockIdx.x;
    const int warp = threadIdx.x >> 5, lane = threadIdx.x & 31;
    float* __restrict__ dmo = out;
    float* __restrict__ cwo = out + (size_t)N * 128;

#pragma unroll
    for (int i = 0; i < 4; ++i) {
        const int n = b * 32 + warp * 4 + i;
        const int2 ij = g_top2i[n];
        const float2 vv = ((const float2*)g_top2v)[n];
        const int rk = g_rank[n], blk = n >> 7;
        const bool k0 = (g_boff[blk * 128 + ij.x]         + (rk & 0xffff)) < capacity;
        const bool k1 = (g_boff[blk * 128 + E_NUM + ij.y] + (rk >> 16))   < capacity;
        const int e0 = lane * 2, e1 = e0 + 1;
        const float d00 = (k0 && ij.x == e0) ? 1.f : 0.f;
        const float d01 = (k1 && ij.y == e0) ? 1.f : 0.f;
        const float d10 = (k0 && ij.x == e1) ? 1.f : 0.f;
        const float d11 = (k1 && ij.y == e1) ? 1.f : 0.f;
        ((float4*)dmo)[(size_t)n * 32 + lane] = make_float4(d00, d01, d10, d11);
        ((float4*)cwo)[(size_t)n * 32 + lane] =
            make_float4(d00 * vv.x, d01 * vv.y, d10 * vv.x, d11 * vv.y);
    }
}

extern "C" void kernel_launch(void* const* d_in, const int* in_sizes, int n_in,
                              void* d_out, int out_size)
{
    const float* x = (const float*)d_in[0];   // [4,4096,2048] f32
    const float* W = (const float*)d_in[1];   // [64,2048]     f32
    float* out = (float*)d_out;

    const int N    = in_sizes[0] / C_DIM;     // 16384
    const int nblk = N / TB;                  // 128
    const int ne2  = N * E_NUM * 2;
    const int capacity = (int)(1.25 * (double)N * 2.0 / (double)E_NUM); // 640

    cudaFuncSetAttribute(router_gemm_kernel,
                         cudaFuncAttributeMaxDynamicSharedMemorySize, DYN_BYTES);

    router_init_kernel<<<1, 128>>>();
    router_prep_kernel<<<512, 256>>>(W);
    router_gemm_kernel<<<nblk, 256, DYN_BYTES>>>(x, N);
    router_scan_kernel<<<1, 512>>>(out, N, nblk, ne2);
    router_write_kernel<<<N / 32, 256>>>(out, N, capacity);
}